// round 1
// baseline (speedup 1.0000x reference)
#include <cuda_runtime.h>

// Problem constants
#define BB 2
#define HH 160
#define WW 192
#define DD 160
#define NN (HH * WW * DD)        // 4,915,200 voxels per batch
#define NTOT (BB * NN)           // 9,830,400 output voxels
#define WD (WW * DD)             // 30,720

// Each thread handles 4 consecutive z voxels (D=160 divisible by 4).
// deformation: [B,H,W,D,3] float -> 3 float4 loads per thread (48B, coalesced)
// X:           [B,H,W,D,2] float -> gather channel 0 (stride-2 scalar loads)
// out:         [B,H,W,D,1] float -> 1 float4 store per thread

__global__ __launch_bounds__(256) void spatial_deformer3d_kernel(
    const float* __restrict__ X,
    const float* __restrict__ def,
    float* __restrict__ out)
{
    int t = blockIdx.x * blockDim.x + threadIdx.x;
    int vox = t * 4;
    if (vox >= NTOT) return;

    // Decompose base voxel index
    int b   = vox / NN;
    int n   = vox - b * NN;
    int h   = n / WD;
    int rem = n - h * WD;
    int w   = rem / DD;
    int zb  = rem - w * DD;   // base z (multiple of 4)

    // Load 4 deformation triplets as 3 float4s (12 floats, contiguous, 16B aligned
    // since vox*3*4B = vox*12 and vox % 4 == 0 -> offset % 48 == 0)
    const float4* dv = reinterpret_cast<const float4*>(def) + (long)t * 3;
    float4 q0 = dv[0];
    float4 q1 = dv[1];
    float4 q2 = dv[2];

    float dx[4] = {q0.x, q0.w, q1.z, q2.y};
    float dy[4] = {q0.y, q1.x, q1.w, q2.z};
    float dz[4] = {q0.z, q1.y, q2.x, q2.w};

    const float* __restrict__ Xb = X + (long)b * NN * 2;

    float4 res;
    float* resp = &res.x;

#pragma unroll
    for (int k = 0; k < 4; k++) {
        float x = (float)w        + dx[k];
        float y = (float)h        + dy[k];
        float z = (float)(zb + k) + dz[k];

        float fx = floorf(x);
        float fy = floorf(y);
        float fz = floorf(z);
        int ix = (int)fx;
        int iy = (int)fy;
        int iz = (int)fz;

        // clamp floor and floor+1 independently (matches reference clip of x0 AND x1)
        int x0 = max(0, min(WW - 1, ix));
        int x1 = max(0, min(WW - 1, ix + 1));
        int y0 = max(0, min(HH - 1, iy));
        int y1 = max(0, min(HH - 1, iy + 1));
        int z0 = max(0, min(DD - 1, iz));
        int z1 = max(0, min(DD - 1, iz + 1));

        // weights use the CLIPPED integer coordinates, per reference
        float wx0 = (float)x1 - x;   // (x1f - x)
        float wx1 = x - (float)x0;   // (x - x0f)
        float wy0 = (float)y1 - y;
        float wy1 = y - (float)y0;
        float wz0 = (float)z1 - z;
        float wz1 = z - (float)z0;

        // gather bases (channel 0 of interleaved 2-channel volume -> *2)
        int i00 = (y0 * WD + x0 * DD) * 2;   // (y0, x0)
        int i01 = (y0 * WD + x1 * DD) * 2;   // (y0, x1)
        int i10 = (y1 * WD + x0 * DD) * 2;   // (y1, x0)
        int i11 = (y1 * WD + x1 * DD) * 2;   // (y1, x1)
        int zo0 = z0 * 2;
        int zo1 = z1 * 2;

        float p000 = __ldg(Xb + i00 + zo0);
        float p001 = __ldg(Xb + i00 + zo1);
        float p010 = __ldg(Xb + i01 + zo0);
        float p011 = __ldg(Xb + i01 + zo1);
        float p100 = __ldg(Xb + i10 + zo0);
        float p101 = __ldg(Xb + i10 + zo1);
        float p110 = __ldg(Xb + i11 + zo0);
        float p111 = __ldg(Xb + i11 + zo1);

        float v00 = fmaf(wz0, p000, wz1 * p001);
        float v01 = fmaf(wz0, p010, wz1 * p011);
        float v10 = fmaf(wz0, p100, wz1 * p101);
        float v11 = fmaf(wz0, p110, wz1 * p111);

        float v0 = fmaf(wx0, v00, wx1 * v01);
        float v1 = fmaf(wx0, v10, wx1 * v11);

        resp[k] = fmaf(wy0, v0, wy1 * v1);
    }

    reinterpret_cast<float4*>(out)[t] = res;
}

extern "C" void kernel_launch(void* const* d_in, const int* in_sizes, int n_in,
                              void* d_out, int out_size) {
    const float* X   = (const float*)d_in[0];   // [2,160,192,160,2]
    const float* def = (const float*)d_in[1];   // [2,160,192,160,3]
    float* out       = (float*)d_out;           // [2,160,192,160,1]

    const int threads_total = NTOT / 4;         // 2,457,600
    const int block = 256;
    const int grid  = (threads_total + block - 1) / block;  // 9600
    spatial_deformer3d_kernel<<<grid, block>>>(X, def, out);
}

// round 2
// speedup vs baseline: 1.2194x; 1.2194x over previous
#include <cuda_runtime.h>

// Problem constants
#define BB 2
#define HH 160
#define WW 192
#define DD 160
#define NN (HH * WW * DD)        // 4,915,200 voxels per batch
#define NTOT (BB * NN)           // 9,830,400 output voxels
#define WD (WW * DD)             // 30,720

// One voxel per thread; consecutive threads = consecutive z.
// This makes the 8 gather loads sector-coherent across a warp:
// lanes that land in the same (y0,x0) row read consecutive z (8B stride in the
// interleaved X layout) -> ~4 lanes share each 32B sector instead of 1.

__global__ __launch_bounds__(256) void spatial_deformer3d_kernel(
    const float* __restrict__ X,
    const float* __restrict__ def,
    float* __restrict__ out)
{
    int t = blockIdx.x * blockDim.x + threadIdx.x;
    if (t >= NTOT) return;

    // Decompose voxel index: t = ((b*H + h)*W + w)*D + z
    int b   = t / NN;
    int n   = t - b * NN;
    int h   = n / WD;
    int rem = n - h * WD;
    int w   = rem / DD;
    int z_i = rem - w * DD;

    const float* dv = def + (long)t * 3;
    float dx = __ldg(dv + 0);
    float dy = __ldg(dv + 1);
    float dz = __ldg(dv + 2);

    const float* __restrict__ Xb = X + (long)b * NN * 2;

    float x = (float)w   + dx;
    float y = (float)h   + dy;
    float z = (float)z_i + dz;

    int ix = (int)floorf(x);
    int iy = (int)floorf(y);
    int iz = (int)floorf(z);

    // clamp floor and floor+1 independently (matches reference clip semantics)
    int x0 = max(0, min(WW - 1, ix));
    int x1 = max(0, min(WW - 1, ix + 1));
    int y0 = max(0, min(HH - 1, iy));
    int y1 = max(0, min(HH - 1, iy + 1));
    int z0 = max(0, min(DD - 1, iz));
    int z1 = max(0, min(DD - 1, iz + 1));

    // weights use the CLIPPED integer coordinates, per reference
    float wx0 = (float)x1 - x;
    float wx1 = x - (float)x0;
    float wy0 = (float)y1 - y;
    float wy1 = y - (float)y0;
    float wz0 = (float)z1 - z;
    float wz1 = z - (float)z0;

    // gather bases (channel 0 of interleaved 2-channel volume -> *2)
    int i00 = (y0 * WD + x0 * DD) * 2;   // (y0, x0)
    int i01 = (y0 * WD + x1 * DD) * 2;   // (y0, x1)
    int i10 = (y1 * WD + x0 * DD) * 2;   // (y1, x0)
    int i11 = (y1 * WD + x1 * DD) * 2;   // (y1, x1)
    int zo0 = z0 * 2;
    int zo1 = z1 * 2;

    float p000 = __ldg(Xb + i00 + zo0);
    float p001 = __ldg(Xb + i00 + zo1);
    float p010 = __ldg(Xb + i01 + zo0);
    float p011 = __ldg(Xb + i01 + zo1);
    float p100 = __ldg(Xb + i10 + zo0);
    float p101 = __ldg(Xb + i10 + zo1);
    float p110 = __ldg(Xb + i11 + zo0);
    float p111 = __ldg(Xb + i11 + zo1);

    float v00 = fmaf(wz0, p000, wz1 * p001);
    float v01 = fmaf(wz0, p010, wz1 * p011);
    float v10 = fmaf(wz0, p100, wz1 * p101);
    float v11 = fmaf(wz0, p110, wz1 * p111);

    float v0 = fmaf(wx0, v00, wx1 * v01);
    float v1 = fmaf(wx0, v10, wx1 * v11);

    out[t] = fmaf(wy0, v0, wy1 * v1);
}

extern "C" void kernel_launch(void* const* d_in, const int* in_sizes, int n_in,
                              void* d_out, int out_size) {
    const float* X   = (const float*)d_in[0];   // [2,160,192,160,2]
    const float* def = (const float*)d_in[1];   // [2,160,192,160,3]
    float* out       = (float*)d_out;           // [2,160,192,160,1]

    const int block = 256;
    const int grid  = (NTOT + block - 1) / block;  // 38400
    spatial_deformer3d_kernel<<<grid, block>>>(X, def, out);
}

// round 3
// speedup vs baseline: 1.2856x; 1.0543x over previous
#include <cuda_runtime.h>

// Problem constants
#define BB 2
#define HH 160
#define WW 192
#define DD 160
#define NN (HH * WW * DD)        // 4,915,200 voxels per batch
#define NTOT (BB * NN)           // 9,830,400 voxels total
#define WD (WW * DD)             // 30,720

// Compact channel-0 volume: contiguous floats, 39.3 MB (fits in L2).
__device__ float g_X0[NTOT];

// ---------------------------------------------------------------------------
// Kernel 1: compact channel 0 out of the interleaved [.,2] layout.
// 4 voxels per thread: two float4 reads -> one float4 write. Fully coalesced.
// ---------------------------------------------------------------------------
__global__ __launch_bounds__(256) void compact_kernel(const float* __restrict__ X)
{
    int t = blockIdx.x * blockDim.x + threadIdx.x;   // NTOT/4 threads
    if (t >= NTOT / 4) return;
    const float4* __restrict__ Xv = reinterpret_cast<const float4*>(X);
    float4 a = Xv[2 * t];         // vox 4t, 4t+1 : (c0, c1, c0, c1)
    float4 b = Xv[2 * t + 1];     // vox 4t+2, 4t+3
    reinterpret_cast<float4*>(g_X0)[t] = make_float4(a.x, a.z, b.x, b.z);
}

// ---------------------------------------------------------------------------
// Kernel 2: trilinear gather from the compact volume.
// One voxel per thread; consecutive threads = consecutive z, so each gather's
// warp footprint is ~5 sectors per (y,x) row, and the z1 load mostly hits L1.
// ---------------------------------------------------------------------------
__global__ __launch_bounds__(256) void spatial_deformer3d_kernel(
    const float* __restrict__ def,
    float* __restrict__ out)
{
    int t = blockIdx.x * blockDim.x + threadIdx.x;
    if (t >= NTOT) return;

    // t = ((b*H + h)*W + w)*D + z
    int b   = t / NN;
    int n   = t - b * NN;
    int h   = n / WD;
    int rem = n - h * WD;
    int w   = rem / DD;
    int z_i = rem - w * DD;

    const float* dv = def + (long)t * 3;
    float dx = __ldg(dv + 0);
    float dy = __ldg(dv + 1);
    float dz = __ldg(dv + 2);

    const float* __restrict__ Xb = g_X0 + b * NN;

    float x = (float)w   + dx;
    float y = (float)h   + dy;
    float z = (float)z_i + dz;

    int ix = (int)floorf(x);
    int iy = (int)floorf(y);
    int iz = (int)floorf(z);

    // clamp floor and floor+1 independently (matches reference clip semantics)
    int x0 = max(0, min(WW - 1, ix));
    int x1 = max(0, min(WW - 1, ix + 1));
    int y0 = max(0, min(HH - 1, iy));
    int y1 = max(0, min(HH - 1, iy + 1));
    int z0 = max(0, min(DD - 1, iz));
    int z1 = max(0, min(DD - 1, iz + 1));

    // weights use the CLIPPED integer coordinates, per reference
    float wx0 = (float)x1 - x;
    float wx1 = x - (float)x0;
    float wy0 = (float)y1 - y;
    float wy1 = y - (float)y0;
    float wz0 = (float)z1 - z;
    float wz1 = z - (float)z0;

    int i00 = y0 * WD + x0 * DD;   // (y0, x0)
    int i01 = y0 * WD + x1 * DD;   // (y0, x1)
    int i10 = y1 * WD + x0 * DD;   // (y1, x0)
    int i11 = y1 * WD + x1 * DD;   // (y1, x1)

    float p000 = __ldg(Xb + i00 + z0);
    float p001 = __ldg(Xb + i00 + z1);
    float p010 = __ldg(Xb + i01 + z0);
    float p011 = __ldg(Xb + i01 + z1);
    float p100 = __ldg(Xb + i10 + z0);
    float p101 = __ldg(Xb + i10 + z1);
    float p110 = __ldg(Xb + i11 + z0);
    float p111 = __ldg(Xb + i11 + z1);

    float v00 = fmaf(wz0, p000, wz1 * p001);
    float v01 = fmaf(wz0, p010, wz1 * p011);
    float v10 = fmaf(wz0, p100, wz1 * p101);
    float v11 = fmaf(wz0, p110, wz1 * p111);

    float v0 = fmaf(wx0, v00, wx1 * v01);
    float v1 = fmaf(wx0, v10, wx1 * v11);

    out[t] = fmaf(wy0, v0, wy1 * v1);
}

extern "C" void kernel_launch(void* const* d_in, const int* in_sizes, int n_in,
                              void* d_out, int out_size) {
    const float* X   = (const float*)d_in[0];   // [2,160,192,160,2]
    const float* def = (const float*)d_in[1];   // [2,160,192,160,3]
    float* out       = (float*)d_out;           // [2,160,192,160,1]

    const int block = 256;
    compact_kernel<<<(NTOT / 4 + block - 1) / block, block>>>(X);
    spatial_deformer3d_kernel<<<(NTOT + block - 1) / block, block>>>(def, out);
}